// round 5
// baseline (speedup 1.0000x reference)
#include <cuda_runtime.h>
#include <cstdint>
#include <cstddef>

#define BQ    2048
#define NTOK  98
#define DIMC  256
#define NHEAD 8
#define HD    32
#define NWIN  64
#define QK_SCALE 0.17677669529663687f   // 32^-0.5

#define NN2   (NTOK*NTOK)               // 9604
#define QKV_ELEMS ((size_t)BQ*NHEAD*NTOK*HD)   // 51,380,224

// ---------------- scratch (static device globals; no cudaMalloc allowed) ----
__device__ float g_q[QKV_ELEMS];
__device__ float g_k[QKV_ELEMS];
__device__ float g_v[QKV_ELEMS];
__device__ float g_o[(size_t)BQ*NTOK*DIMC];
__device__ float g_bias[NHEAD*NN2];
// weights transposed [n][k] AND pre-split into tf32 hi/lo planes
__device__ float g_wt_qkv_hi[768*256];
__device__ float g_wt_qkv_lo[768*256];
__device__ float g_wt_proj_hi[256*256];
__device__ float g_wt_proj_lo[256*256];

// ======================= helpers =============================================
__device__ __forceinline__ uint32_t smem_to_u32(const void* p) {
    uint32_t a;
    asm("{ .reg .u64 t; cvta.to.shared.u64 t, %1; cvt.u32.u64 %0, t; }"
        : "=r"(a) : "l"(p));
    return a;
}
__device__ __forceinline__ void cp_async16(uint32_t dst, const void* src) {
    asm volatile("cp.async.cg.shared.global [%0], [%1], 16;"
                 :: "r"(dst), "l"(src) : "memory");
}
#define CP_COMMIT() asm volatile("cp.async.commit_group;" ::: "memory")
#define CP_WAIT(n)  asm volatile("cp.async.wait_group %0;" :: "n"(n) : "memory")

// tf32 warp MMA: D(16x8) += A(16x8) * B(8x8)
__device__ __forceinline__ void mma_tf32(float* d, const uint32_t* a, const uint32_t* b) {
    asm volatile(
        "mma.sync.aligned.m16n8k8.row.col.f32.tf32.tf32.f32 "
        "{%0,%1,%2,%3}, {%4,%5,%6,%7}, {%8,%9}, {%0,%1,%2,%3};"
        : "+f"(d[0]), "+f"(d[1]), "+f"(d[2]), "+f"(d[3])
        : "r"(a[0]), "r"(a[1]), "r"(a[2]), "r"(a[3]), "r"(b[0]), "r"(b[1]));
}

// Dekker-style fp32 -> tf32 hi/lo split. hi = rna(tf32), lo = f - hi (exact).
__device__ __forceinline__ void split_tf32(float f, uint32_t& hi, uint32_t& lo) {
    uint32_t h;
    asm("cvt.rna.tf32.f32 %0, %1;" : "=r"(h) : "f"(f));
    hi = h;
    lo = __float_as_uint(f - __uint_as_float(h));
}

// ---------------- kernel: transpose + pre-split weights ---------------------
__global__ void transpose_w_kernel(const float* __restrict__ W, int N, int which)
{
    __shared__ float t[32][33];
    float* Wh = which ? g_wt_proj_hi : g_wt_qkv_hi;
    float* Wl = which ? g_wt_proj_lo : g_wt_qkv_lo;
    int n0 = blockIdx.x * 32, k0 = blockIdx.y * 32;
    int tx = threadIdx.x, ty = threadIdx.y;    // 32 x 8
    #pragma unroll
    for (int j = 0; j < 4; ++j)
        t[ty + j*8][tx] = W[(size_t)(k0 + ty + j*8) * N + n0 + tx];
    __syncthreads();
    #pragma unroll
    for (int j = 0; j < 4; ++j) {
        float w = t[tx][ty + j*8];
        uint32_t hi, lo;
        split_tf32(w, hi, lo);
        size_t idx = (size_t)(n0 + ty + j*8) * 256 + k0 + tx;
        Wh[idx] = __uint_as_float(hi);
        Wl[idx] = __uint_as_float(lo);
    }
}

// ---------------- kernel: build per-head relative-position bias -------------
__global__ void bias_build_kernel(const float* __restrict__ table,
                                  const int*   __restrict__ rel)
{
    int t = blockIdx.x * blockDim.x + threadIdx.x;
    if (t < NHEAD * NN2) {
        int h  = t / NN2;
        int ij = t - h * NN2;
        g_bias[t] = table[rel[ij] * NHEAD + h];
    }
}

// ---------------- 3xTF32 mma.sync GEMM: 128x128 tile, K=256, cp.async x2 ----
// smem per buffer: A raw + B_hi + B_lo, each 128x36 floats.
#define GPITCH 36
#define TILE_F (128 * GPITCH)                 // 4608 floats
#define BUF_F  (3 * TILE_F)                   // 13824 floats per buffer
#define GEMM_SMEM (2 * BUF_F * 4)             // 110592 bytes

template<bool IS_QKV>
__global__ void __launch_bounds__(256, 2)
gemm_mma_kernel(const float* __restrict__ Aq,   // QKV: x; proj: unused
                const float* __restrict__ bias,
                float* __restrict__ out)        // proj: d_out; QKV: unused
{
    extern __shared__ float smf[];
    uint32_t sb = smem_to_u32(smf);
    const int tid = threadIdx.x;
    const int wid = tid >> 5, lane = tid & 31;
    const int g = lane >> 2, tg = lane & 3;
    const int bm = blockIdx.x * 128;
    const int bn = blockIdx.y * 128;

    const float* A   = IS_QKV ? Aq : g_o;
    const float* Bth = IS_QKV ? g_wt_qkv_hi : g_wt_proj_hi;
    const float* Btl = IS_QKV ? g_wt_qkv_lo : g_wt_proj_lo;
    const int K = 256;

    const int r_  = tid >> 3;          // 0..31 base row
    const int c4_ = tid & 7;           // 0..7 16B segment within 32-f32 chunk

    float acc[4][4][4];
    #pragma unroll
    for (int am = 0; am < 4; ++am)
        #pragma unroll
        for (int an = 0; an < 4; ++an)
            #pragma unroll
            for (int j = 0; j < 4; ++j) acc[am][an][j] = 0.0f;

    auto issue = [&](int c, int buf) {
        int k0 = c * 32;
        uint32_t base = sb + (uint32_t)buf * (BUF_F * 4);
        #pragma unroll
        for (int i = 0; i < 4; ++i) {
            int r = r_ + i * 32;
            cp_async16(base + (uint32_t)(r * GPITCH * 4 + c4_ * 16),
                       A + (size_t)(bm + r) * K + k0 + c4_ * 4);
        }
        #pragma unroll
        for (int i = 0; i < 4; ++i) {
            int r = r_ + i * 32;
            cp_async16(base + (uint32_t)(TILE_F * 4 + r * GPITCH * 4 + c4_ * 16),
                       Bth + (size_t)(bn + r) * K + k0 + c4_ * 4);
        }
        #pragma unroll
        for (int i = 0; i < 4; ++i) {
            int r = r_ + i * 32;
            cp_async16(base + (uint32_t)(2 * TILE_F * 4 + r * GPITCH * 4 + c4_ * 16),
                       Btl + (size_t)(bn + r) * K + k0 + c4_ * 4);
        }
    };

    issue(0, 0);
    CP_COMMIT();

    const int mw = (wid >> 2) * 64;
    const int nw = (wid & 3) * 32;

    #pragma unroll 1
    for (int c = 0; c < 8; ++c) {
        if (c + 1 < 8) { issue(c + 1, (c + 1) & 1); CP_COMMIT(); CP_WAIT(1); }
        else           { CP_WAIT(0); }
        __syncthreads();

        const float* As = smf + (c & 1) * BUF_F;
        const float* Bh = As + TILE_F;
        const float* Bl = As + 2 * TILE_F;

        #pragma unroll
        for (int s = 0; s < 4; ++s) {
            int k0 = s * 8 + tg;
            // B fragments: pre-split planes, direct loads
            uint32_t bh[4][2], bl[4][2];
            #pragma unroll
            for (int an = 0; an < 4; ++an) {
                int base = (nw + 8 * an + g) * GPITCH + k0;
                bh[an][0] = __float_as_uint(Bh[base]);
                bh[an][1] = __float_as_uint(Bh[base + 4]);
                bl[an][0] = __float_as_uint(Bl[base]);
                bl[an][1] = __float_as_uint(Bl[base + 4]);
            }
            #pragma unroll
            for (int am = 0; am < 4; ++am) {
                int base = (mw + 16 * am + g) * GPITCH + k0;
                uint32_t ah[4], al[4];
                split_tf32(As[base],                  ah[0], al[0]);
                split_tf32(As[base + 8 * GPITCH],     ah[1], al[1]);
                split_tf32(As[base + 4],              ah[2], al[2]);
                split_tf32(As[base + 8 * GPITCH + 4], ah[3], al[3]);
                #pragma unroll
                for (int an = 0; an < 4; ++an) {
                    mma_tf32(acc[am][an], al, bh[an]);   // lo*hi
                    mma_tf32(acc[am][an], ah, bl[an]);   // hi*lo
                    mma_tf32(acc[am][an], ah, bh[an]);   // hi*hi
                }
            }
        }
        __syncthreads();
    }

    // -------- epilogue --------
    #pragma unroll
    for (int am = 0; am < 4; ++am) {
        #pragma unroll
        for (int half = 0; half < 2; ++half) {
            int m = bm + mw + 16 * am + g + 8 * half;
            if (IS_QKV) {
                int bwin = m / NTOK;
                int nn   = m - bwin * NTOK;
                #pragma unroll
                for (int an = 0; an < 4; ++an) {
                    int gcol = bn + nw + 8 * an + 2 * tg;
                    int sel  = gcol >> 8;
                    int h    = (gcol >> 5) & 7;
                    int d    = gcol & 31;
                    float* dst = (sel == 0 ? g_q : (sel == 1 ? g_k : g_v))
                               + (((size_t)bwin * NHEAD + h) * NTOK + nn) * HD + d;
                    float sc = (sel == 0) ? QK_SCALE : 1.0f;
                    float2 v;
                    v.x = (acc[am][an][2*half+0] + bias[gcol+0]) * sc;
                    v.y = (acc[am][an][2*half+1] + bias[gcol+1]) * sc;
                    *(float2*)dst = v;
                }
            } else {
                #pragma unroll
                for (int an = 0; an < 4; ++an) {
                    int gcol = bn + nw + 8 * an + 2 * tg;
                    float2 v;
                    v.x = acc[am][an][2*half+0] + bias[gcol+0];
                    v.y = acc[am][an][2*half+1] + bias[gcol+1];
                    *(float2*)(out + (size_t)m * DIMC + gcol) = v;
                }
            }
        }
    }
}

// ---------------- kernel: fused windowed attention (vectorized) --------------
// Q/K/V smem pitch 36 floats (16B-aligned rows), S pitch 100.
#define QP   36
#define SP   100
#define SM_KOFF 3528                    // 98*36
#define SM_SOFF 7056                    // 2*98*36
#define ATTN_SMEM_BYTES ((SM_SOFF + 98 * SP) * 4)   // 67424 bytes

__global__ void __launch_bounds__(256) attn_kernel(const float* __restrict__ mask)
{
    extern __shared__ float sm[];
    float* Qs = sm;                 // later reused for V
    float* Ks = sm + SM_KOFF;
    float* S  = sm + SM_SOFF;

    int bid = blockIdx.x;
    int b = bid >> 3, h = bid & 7;
    int w = b & (NWIN - 1);
    int tid = threadIdx.x;
    int tx = tid & 15, ty = tid >> 4;

    const float* qp = g_q + (size_t)bid * (NTOK * HD);
    const float* kp = g_k + (size_t)bid * (NTOK * HD);
    const float* vp = g_v + (size_t)bid * (NTOK * HD);

    // load Q, K (98x32) into pitch-36 smem
    for (int t = tid; t < (NTOK * HD) / 4; t += 256) {     // 784 float4
        float4 q4 = ((const float4*)qp)[t];
        float4 k4 = ((const float4*)kp)[t];
        int i = t >> 3, seg = (t & 7) * 4;
        *(float4*)&Qs[i*QP + seg] = q4;
        *(float4*)&Ks[i*QP + seg] = k4;
    }
    __syncthreads();

    // --- S = Q K^T, 7x7 strided micro-tile, k blocked by 4 (float4 LDS) ---
    float acc[7][7];
    #pragma unroll
    for (int r = 0; r < 7; ++r)
        #pragma unroll
        for (int s2 = 0; s2 < 7; ++s2) acc[r][s2] = 0.0f;

    #pragma unroll
    for (int kk = 0; kk < HD; kk += 4) {
        float4 qv[7];
        #pragma unroll
        for (int r = 0; r < 7; ++r) {
            int i = ty + 16*r; i = (i < NTOK) ? i : (NTOK - 1);
            qv[r] = *(const float4*)&Qs[i*QP + kk];
        }
        #pragma unroll
        for (int s2 = 0; s2 < 7; ++s2) {
            int j = tx + 16*s2; j = (j < NTOK) ? j : (NTOK - 1);
            float4 kv = *(const float4*)&Ks[j*QP + kk];
            #pragma unroll
            for (int r = 0; r < 7; ++r) {
                float t0 = fmaf(qv[r].x, kv.x, acc[r][s2]);
                float t1 = fmaf(qv[r].y, kv.y, t0);
                float t2 = fmaf(qv[r].z, kv.z, t1);
                acc[r][s2] = fmaf(qv[r].w, kv.w, t2);
            }
        }
    }

    const float* bptr = g_bias + h * NN2;
    const float* mptr = mask + w * NN2;
    #pragma unroll
    for (int r = 0; r < 7; ++r) {
        int i = ty + 16*r;
        if (i < NTOK) {
            #pragma unroll
            for (int s2 = 0; s2 < 7; ++s2) {
                int j = tx + 16*s2;
                if (j < NTOK)
                    S[i*SP + j] = acc[r][s2] + bptr[i*NTOK + j] + mptr[i*NTOK + j];
            }
        }
    }
    __syncthreads();

    // load V into Qs region (Q is dead); overlaps with softmax
    for (int t = tid; t < (NTOK * HD) / 4; t += 256) {
        float4 v4 = ((const float4*)vp)[t];
        int i = t >> 3, seg = (t & 7) * 4;
        *(float4*)&Qs[i*QP + seg] = v4;
    }

    int warp = tid >> 5, lane = tid & 31;
    for (int r = warp; r < NTOK; r += 8) {
        float* row = S + r * SP;
        float v0 = row[lane];
        float v1 = row[32 + lane];
        float v2 = row[64 + lane];
        float v3 = (lane < 2) ? row[96 + lane] : -1e30f;
        float mx = fmaxf(fmaxf(v0, v1), fmaxf(v2, v3));
        #pragma unroll
        for (int o = 16; o > 0; o >>= 1) mx = fmaxf(mx, __shfl_xor_sync(0xffffffffu, mx, o));
        float e0 = __expf(v0 - mx), e1 = __expf(v1 - mx), e2 = __expf(v2 - mx);
        float e3 = (lane < 2) ? __expf(v3 - mx) : 0.0f;
        float sum = e0 + e1 + e2 + e3;
        #pragma unroll
        for (int o = 16; o > 0; o >>= 1) sum += __shfl_xor_sync(0xffffffffu, sum, o);
        float inv = 1.0f / sum;
        row[lane]      = e0 * inv;
        row[32 + lane] = e1 * inv;
        row[64 + lane] = e2 * inv;
        if (lane < 2) row[96 + lane] = e3 * inv;
    }
    __syncthreads();

    // --- O = P V : j blocked by 4 with float4 S loads ---
    float o0[7], o1[7];
    #pragma unroll
    for (int r = 0; r < 7; ++r) { o0[r] = 0.0f; o1[r] = 0.0f; }

    #pragma unroll 4
    for (int j = 0; j < 96; j += 4) {
        float4 sj[7];
        #pragma unroll
        for (int r = 0; r < 7; ++r) {
            int i = ty + 16*r; i = (i < NTOK) ? i : (NTOK - 1);
            sj[r] = *(const float4*)&S[i*SP + j];
        }
        float va[4], vb[4];
        #pragma unroll
        for (int u = 0; u < 4; ++u) {
            va[u] = Qs[(j+u)*QP + tx];
            vb[u] = Qs[(j+u)*QP + 16 + tx];
        }
        #pragma unroll
        for (int r = 0; r < 7; ++r) {
            const float* sp2 = (const float*)&sj[r];
            #pragma unroll
            for (int u = 0; u < 4; ++u) {
                o0[r] = fmaf(sp2[u], va[u], o0[r]);
                o1[r] = fmaf(sp2[u], vb[u], o1[r]);
            }
        }
    }
    // tail: j = 96, 97
    #pragma unroll
    for (int j = 96; j < NTOK; ++j) {
        float v0 = Qs[j*QP + tx];
        float v1 = Qs[j*QP + 16 + tx];
        #pragma unroll
        for (int r = 0; r < 7; ++r) {
            int i = ty + 16*r; i = (i < NTOK) ? i : (NTOK - 1);
            float p = S[i*SP + j];
            o0[r] = fmaf(p, v0, o0[r]);
            o1[r] = fmaf(p, v1, o1[r]);
        }
    }

    float* op = g_o + (size_t)b * NTOK * DIMC + h * HD;
    #pragma unroll
    for (int r = 0; r < 7; ++r) {
        int i = ty + 16*r;
        if (i < NTOK) {
            op[(size_t)i * DIMC + tx]      = o0[r];
            op[(size_t)i * DIMC + 16 + tx] = o1[r];
        }
    }
}

// ---------------- launch -----------------------------------------------------
extern "C" void kernel_launch(void* const* d_in, const int* in_sizes, int n_in,
                              void* d_out, int out_size)
{
    const float* x          = (const float*)d_in[0];
    const float* mask       = (const float*)d_in[1];
    const float* qkv_w      = (const float*)d_in[2];
    const float* qkv_b      = (const float*)d_in[3];
    const float* proj_w     = (const float*)d_in[4];
    const float* proj_b     = (const float*)d_in[5];
    const float* bias_table = (const float*)d_in[6];
    const int*   rel_index  = (const int*)d_in[7];
    float* out = (float*)d_out;

    cudaFuncSetAttribute(gemm_mma_kernel<true>,
                         cudaFuncAttributeMaxDynamicSharedMemorySize, GEMM_SMEM);
    cudaFuncSetAttribute(gemm_mma_kernel<false>,
                         cudaFuncAttributeMaxDynamicSharedMemorySize, GEMM_SMEM);
    cudaFuncSetAttribute(attn_kernel,
                         cudaFuncAttributeMaxDynamicSharedMemorySize, ATTN_SMEM_BYTES);

    transpose_w_kernel<<<dim3(24, 8), dim3(32, 8)>>>(qkv_w, 768, 0);
    transpose_w_kernel<<<dim3(8, 8),  dim3(32, 8)>>>(proj_w, 256, 1);
    bias_build_kernel<<<(NHEAD * NN2 + 255) / 256, 256>>>(bias_table, rel_index);

    gemm_mma_kernel<true><<<dim3(1568, 6), 256, GEMM_SMEM>>>(x, qkv_b, nullptr);

    attn_kernel<<<BQ * NHEAD, 256, ATTN_SMEM_BYTES>>>(mask);

    gemm_mma_kernel<false><<<dim3(1568, 2), 256, GEMM_SMEM>>>(nullptr, proj_b, out);
}

// round 6
// speedup vs baseline: 1.0562x; 1.0562x over previous
#include <cuda_runtime.h>
#include <cstdint>
#include <cstddef>

#define BQ    2048
#define NTOK  98
#define DIMC  256
#define NHEAD 8
#define HD    32
#define NWIN  64
#define QK_SCALE 0.17677669529663687f   // 32^-0.5

#define NN2   (NTOK*NTOK)               // 9604
#define QKV_ELEMS ((size_t)BQ*NHEAD*NTOK*HD)   // 51,380,224

// ---------------- scratch (static device globals; no cudaMalloc allowed) ----
__device__ float g_q[QKV_ELEMS];
__device__ float g_k[QKV_ELEMS];
__device__ float g_v[QKV_ELEMS];
__device__ float g_o[(size_t)BQ*NTOK*DIMC];
__device__ float g_bias[NHEAD*NN2];
__device__ float g_wt_qkv[768*256];     // qkv_w transposed: [n][k]
__device__ float g_wt_proj[256*256];    // proj_w transposed: [n][k]

// ======================= helpers =============================================
__device__ __forceinline__ uint32_t smem_to_u32(const void* p) {
    uint32_t a;
    asm("{ .reg .u64 t; cvta.to.shared.u64 t, %1; cvt.u32.u64 %0, t; }"
        : "=r"(a) : "l"(p));
    return a;
}
__device__ __forceinline__ void cp_async16(uint32_t dst, const void* src) {
    asm volatile("cp.async.cg.shared.global [%0], [%1], 16;"
                 :: "r"(dst), "l"(src) : "memory");
}
#define CP_COMMIT() asm volatile("cp.async.commit_group;" ::: "memory")
#define CP_WAIT(n)  asm volatile("cp.async.wait_group %0;" :: "n"(n) : "memory")

// tf32 warp MMA: D(16x8) += A(16x8) * B(8x8)
__device__ __forceinline__ void mma_tf32(float* d, const uint32_t* a, const uint32_t* b) {
    asm volatile(
        "mma.sync.aligned.m16n8k8.row.col.f32.tf32.tf32.f32 "
        "{%0,%1,%2,%3}, {%4,%5,%6,%7}, {%8,%9}, {%0,%1,%2,%3};"
        : "+f"(d[0]), "+f"(d[1]), "+f"(d[2]), "+f"(d[3])
        : "r"(a[0]), "r"(a[1]), "r"(a[2]), "r"(a[3]), "r"(b[0]), "r"(b[1]));
}

// Dekker-style fp32 -> tf32 hi/lo split. hi = rna(tf32), lo = f - hi (exact).
__device__ __forceinline__ void split_tf32(float f, uint32_t& hi, uint32_t& lo) {
    uint32_t h;
    asm("cvt.rna.tf32.f32 %0, %1;" : "=r"(h) : "f"(f));
    hi = h;
    lo = __float_as_uint(f - __uint_as_float(h));
}

// FFMA-only exp (avoids the MUFU.EX2 throughput floor; rel err ~2.4e-6).
// exp(x) = 2^(x*log2e); n = round(t), f = t-n in [-0.5,0.5]; degree-5 poly for 2^f.
__device__ __forceinline__ float fast_exp(float x) {
    x = fmaxf(x, -87.0f);
    float t = x * 1.4426950408889634f;
    float nb = t + 12582912.0f;                 // magic round-to-nearest
    float n  = nb - 12582912.0f;
    float f  = t - n;
    float p = 1.3333558146428443e-3f;
    p = fmaf(p, f, 9.6181291076284771e-3f);
    p = fmaf(p, f, 5.5504108664821580e-2f);
    p = fmaf(p, f, 2.4022650695910071e-1f);
    p = fmaf(p, f, 6.9314718055994531e-1f);
    p = fmaf(p, f, 1.0f);
    return __int_as_float(__float_as_int(p) + (__float_as_int(nb) << 23));
}

// ---------------- kernel: transpose weights (Wt[n][k] = W[k][n]) ------------
__global__ void transpose_w_kernel(const float* __restrict__ W, int N, int which)
{
    __shared__ float t[32][33];
    float* Wt = which ? g_wt_proj : g_wt_qkv;
    int n0 = blockIdx.x * 32, k0 = blockIdx.y * 32;
    int tx = threadIdx.x, ty = threadIdx.y;    // 32 x 8
    #pragma unroll
    for (int j = 0; j < 4; ++j)
        t[ty + j*8][tx] = W[(size_t)(k0 + ty + j*8) * N + n0 + tx];
    __syncthreads();
    #pragma unroll
    for (int j = 0; j < 4; ++j)
        Wt[(size_t)(n0 + ty + j*8) * 256 + k0 + tx] = t[tx][ty + j*8];
}

// ---------------- kernel: build per-head relative-position bias -------------
__global__ void bias_build_kernel(const float* __restrict__ table,
                                  const int*   __restrict__ rel)
{
    int t = blockIdx.x * blockDim.x + threadIdx.x;
    if (t < NHEAD * NN2) {
        int h  = t / NN2;
        int ij = t - h * NN2;
        g_bias[t] = table[rel[ij] * NHEAD + h];
    }
}

// ---------------- 3xTF32 mma.sync GEMM: 128x128 tile, K=256, cp.async x2 ----
// smem per buffer: A[128][36] + B[128][36] floats = 36864 B; two buffers.
#define GPITCH 36
#define TILE_F (128 * GPITCH)                 // 4608 floats
#define BUF_F  (2 * TILE_F)                   // 9216 floats per buffer
#define GEMM_SMEM (2 * BUF_F * 4)             // 73728 bytes

template<bool IS_QKV>
__global__ void __launch_bounds__(256, 2)
gemm_mma_kernel(const float* __restrict__ Aq,   // QKV: x; proj: unused
                const float* __restrict__ bias,
                float* __restrict__ out)        // proj: d_out; QKV: unused
{
    extern __shared__ float smf[];
    uint32_t sb = smem_to_u32(smf);
    const int tid = threadIdx.x;
    const int wid = tid >> 5, lane = tid & 31;
    const int g = lane >> 2, tg = lane & 3;
    const int bm = blockIdx.x * 128;
    const int bn = blockIdx.y * 128;

    const float* A  = IS_QKV ? Aq : g_o;
    const float* Bt = IS_QKV ? g_wt_qkv : g_wt_proj;
    const int K = 256;

    const int r_  = tid >> 3;          // 0..31 base row
    const int c4_ = tid & 7;           // 0..7 16B segment within 32-f32 chunk

    float acc[4][4][4];
    #pragma unroll
    for (int am = 0; am < 4; ++am)
        #pragma unroll
        for (int an = 0; an < 4; ++an)
            #pragma unroll
            for (int j = 0; j < 4; ++j) acc[am][an][j] = 0.0f;

    auto issue = [&](int c, int buf) {
        int k0 = c * 32;
        uint32_t base = sb + (uint32_t)buf * (BUF_F * 4);
        #pragma unroll
        for (int i = 0; i < 4; ++i) {
            int r = r_ + i * 32;
            cp_async16(base + (uint32_t)(r * GPITCH * 4 + c4_ * 16),
                       A + (size_t)(bm + r) * K + k0 + c4_ * 4);
        }
        #pragma unroll
        for (int i = 0; i < 4; ++i) {
            int r = r_ + i * 32;
            cp_async16(base + (uint32_t)(TILE_F * 4 + r * GPITCH * 4 + c4_ * 16),
                       Bt + (size_t)(bn + r) * K + k0 + c4_ * 4);
        }
    };

    issue(0, 0);
    CP_COMMIT();

    const int mw = (wid >> 2) * 64;
    const int nw = (wid & 3) * 32;

    #pragma unroll 1
    for (int c = 0; c < 8; ++c) {
        if (c + 1 < 8) { issue(c + 1, (c + 1) & 1); CP_COMMIT(); CP_WAIT(1); }
        else           { CP_WAIT(0); }
        __syncthreads();

        const float* As = smf + (c & 1) * BUF_F;
        const float* Bs = As + TILE_F;

        #pragma unroll
        for (int s = 0; s < 4; ++s) {
            int k0 = s * 8 + tg;
            // split B fragments once per k-step
            uint32_t bh[4][2], bl[4][2];
            #pragma unroll
            for (int an = 0; an < 4; ++an) {
                int base = (nw + 8 * an + g) * GPITCH + k0;
                split_tf32(Bs[base],     bh[an][0], bl[an][0]);
                split_tf32(Bs[base + 4], bh[an][1], bl[an][1]);
            }
            #pragma unroll
            for (int am = 0; am < 4; ++am) {
                int base = (mw + 16 * am + g) * GPITCH + k0;
                uint32_t ah[4], al[4];
                split_tf32(As[base],                  ah[0], al[0]);
                split_tf32(As[base + 8 * GPITCH],     ah[1], al[1]);
                split_tf32(As[base + 4],              ah[2], al[2]);
                split_tf32(As[base + 8 * GPITCH + 4], ah[3], al[3]);
                #pragma unroll
                for (int an = 0; an < 4; ++an) {
                    mma_tf32(acc[am][an], al, bh[an]);   // lo*hi
                    mma_tf32(acc[am][an], ah, bl[an]);   // hi*lo
                    mma_tf32(acc[am][an], ah, bh[an]);   // hi*hi
                }
            }
        }
        __syncthreads();
    }

    // -------- epilogue --------
    #pragma unroll
    for (int am = 0; am < 4; ++am) {
        #pragma unroll
        for (int half = 0; half < 2; ++half) {
            int m = bm + mw + 16 * am + g + 8 * half;
            if (IS_QKV) {
                int bwin = m / NTOK;
                int nn   = m - bwin * NTOK;
                #pragma unroll
                for (int an = 0; an < 4; ++an) {
                    int gcol = bn + nw + 8 * an + 2 * tg;
                    int sel  = gcol >> 8;
                    int h    = (gcol >> 5) & 7;
                    int d    = gcol & 31;
                    float* dst = (sel == 0 ? g_q : (sel == 1 ? g_k : g_v))
                               + (((size_t)bwin * NHEAD + h) * NTOK + nn) * HD + d;
                    float sc = (sel == 0) ? QK_SCALE : 1.0f;
                    float2 v;
                    v.x = (acc[am][an][2*half+0] + bias[gcol+0]) * sc;
                    v.y = (acc[am][an][2*half+1] + bias[gcol+1]) * sc;
                    *(float2*)dst = v;
                }
            } else {
                #pragma unroll
                for (int an = 0; an < 4; ++an) {
                    int gcol = bn + nw + 8 * an + 2 * tg;
                    float2 v;
                    v.x = acc[am][an][2*half+0] + bias[gcol+0];
                    v.y = acc[am][an][2*half+1] + bias[gcol+1];
                    *(float2*)(out + (size_t)m * DIMC + gcol) = v;
                }
            }
        }
    }
}

// ---------------- kernel: fused windowed attention --------------------------
#define SM_Q 0
#define SM_K 3234
#define SM_S 6468
#define ATTN_SMEM_BYTES (16072 * 4)

__global__ void __launch_bounds__(256) attn_kernel(const float* __restrict__ mask)
{
    extern __shared__ float sm[];
    float* Qs = sm + SM_Q;
    float* Ks = sm + SM_K;
    float* S  = sm + SM_S;

    int bid = blockIdx.x;
    int b = bid >> 3, h = bid & 7;
    int w = b & (NWIN - 1);
    int tid = threadIdx.x;
    int tx = tid & 15, ty = tid >> 4;

    const float* qp = g_q + (size_t)bid * (NTOK * HD);
    const float* kp = g_k + (size_t)bid * (NTOK * HD);
    const float* vp = g_v + (size_t)bid * (NTOK * HD);

    for (int t = tid; t < (NTOK * HD) / 4; t += 256) {
        float4 q4 = ((const float4*)qp)[t];
        float4 k4 = ((const float4*)kp)[t];
        int i = t >> 3, seg = (t & 7) * 4;
        float* qd = Qs + i*33 + seg;
        float* kd = Ks + i*33 + seg;
        qd[0]=q4.x; qd[1]=q4.y; qd[2]=q4.z; qd[3]=q4.w;
        kd[0]=k4.x; kd[1]=k4.y; kd[2]=k4.z; kd[3]=k4.w;
    }
    __syncthreads();

    float acc[7][7];
    #pragma unroll
    for (int r = 0; r < 7; ++r)
        #pragma unroll
        for (int s2 = 0; s2 < 7; ++s2) acc[r][s2] = 0.0f;

    for (int kk = 0; kk < HD; ++kk) {
        float qv[7], kv[7];
        #pragma unroll
        for (int r = 0; r < 7; ++r) {
            int i = ty + 16*r; i = (i < NTOK) ? i : (NTOK - 1);
            qv[r] = Qs[i*33 + kk];
        }
        #pragma unroll
        for (int s2 = 0; s2 < 7; ++s2) {
            int j = tx + 16*s2; j = (j < NTOK) ? j : (NTOK - 1);
            kv[s2] = Ks[j*33 + kk];
        }
        #pragma unroll
        for (int r = 0; r < 7; ++r)
            #pragma unroll
            for (int s2 = 0; s2 < 7; ++s2)
                acc[r][s2] = fmaf(qv[r], kv[s2], acc[r][s2]);
    }

    const float* bptr = g_bias + h * NN2;
    const float* mptr = mask + w * NN2;
    #pragma unroll
    for (int r = 0; r < 7; ++r) {
        int i = ty + 16*r;
        if (i < NTOK) {
            #pragma unroll
            for (int s2 = 0; s2 < 7; ++s2) {
                int j = tx + 16*s2;
                if (j < NTOK)
                    S[i*NTOK + j] = acc[r][s2] + bptr[i*NTOK + j] + mptr[i*NTOK + j];
            }
        }
    }
    __syncthreads();

    for (int t = tid; t < (NTOK * HD) / 4; t += 256) {
        float4 v4 = ((const float4*)vp)[t];
        int i = t >> 3, seg = (t & 7) * 4;
        float* vd = Qs + i*33 + seg;
        vd[0]=v4.x; vd[1]=v4.y; vd[2]=v4.z; vd[3]=v4.w;
    }

    int warp = tid >> 5, lane = tid & 31;
    for (int r = warp; r < NTOK; r += 8) {
        float* row = S + r * NTOK;
        float v0 = row[lane];
        float v1 = row[32 + lane];
        float v2 = row[64 + lane];
        float v3 = (lane < 2) ? row[96 + lane] : -1e30f;
        float mx = fmaxf(fmaxf(v0, v1), fmaxf(v2, v3));
        #pragma unroll
        for (int o = 16; o > 0; o >>= 1) mx = fmaxf(mx, __shfl_xor_sync(0xffffffffu, mx, o));
        float e0 = fast_exp(v0 - mx), e1 = fast_exp(v1 - mx), e2 = fast_exp(v2 - mx);
        float e3 = (lane < 2) ? fast_exp(v3 - mx) : 0.0f;
        float sum = e0 + e1 + e2 + e3;
        #pragma unroll
        for (int o = 16; o > 0; o >>= 1) sum += __shfl_xor_sync(0xffffffffu, sum, o);
        float inv = 1.0f / sum;
        row[lane]      = e0 * inv;
        row[32 + lane] = e1 * inv;
        row[64 + lane] = e2 * inv;
        if (lane < 2) row[96 + lane] = e3 * inv;
    }
    __syncthreads();

    float o0[7], o1[7];
    #pragma unroll
    for (int r = 0; r < 7; ++r) { o0[r] = 0.0f; o1[r] = 0.0f; }

    for (int j = 0; j < NTOK; ++j) {
        float v0 = Qs[j*33 + tx];
        float v1 = Qs[j*33 + 16 + tx];
        #pragma unroll
        for (int r = 0; r < 7; ++r) {
            int i = ty + 16*r;
            if (i < NTOK) {
                float p = S[i*NTOK + j];
                o0[r] = fmaf(p, v0, o0[r]);
                o1[r] = fmaf(p, v1, o1[r]);
            }
        }
    }

    float* op = g_o + (size_t)b * NTOK * DIMC + h * HD;
    #pragma unroll
    for (int r = 0; r < 7; ++r) {
        int i = ty + 16*r;
        if (i < NTOK) {
            op[(size_t)i * DIMC + tx]      = o0[r];
            op[(size_t)i * DIMC + 16 + tx] = o1[r];
        }
    }
}

// ---------------- launch -----------------------------------------------------
extern "C" void kernel_launch(void* const* d_in, const int* in_sizes, int n_in,
                              void* d_out, int out_size)
{
    const float* x          = (const float*)d_in[0];
    const float* mask       = (const float*)d_in[1];
    const float* qkv_w      = (const float*)d_in[2];
    const float* qkv_b      = (const float*)d_in[3];
    const float* proj_w     = (const float*)d_in[4];
    const float* proj_b     = (const float*)d_in[5];
    const float* bias_table = (const float*)d_in[6];
    const int*   rel_index  = (const int*)d_in[7];
    float* out = (float*)d_out;

    cudaFuncSetAttribute(gemm_mma_kernel<true>,
                         cudaFuncAttributeMaxDynamicSharedMemorySize, GEMM_SMEM);
    cudaFuncSetAttribute(gemm_mma_kernel<false>,
                         cudaFuncAttributeMaxDynamicSharedMemorySize, GEMM_SMEM);
    cudaFuncSetAttribute(attn_kernel,
                         cudaFuncAttributeMaxDynamicSharedMemorySize, ATTN_SMEM_BYTES);

    transpose_w_kernel<<<dim3(24, 8), dim3(32, 8)>>>(qkv_w, 768, 0);
    transpose_w_kernel<<<dim3(8, 8),  dim3(32, 8)>>>(proj_w, 256, 1);
    bias_build_kernel<<<(NHEAD * NN2 + 255) / 256, 256>>>(bias_table, rel_index);

    gemm_mma_kernel<true><<<dim3(1568, 6), 256, GEMM_SMEM>>>(x, qkv_b, nullptr);

    attn_kernel<<<BQ * NHEAD, 256, ATTN_SMEM_BYTES>>>(mask);

    gemm_mma_kernel<false><<<dim3(1568, 2), 256, GEMM_SMEM>>>(nullptr, proj_b, out);
}

// round 7
// speedup vs baseline: 1.5729x; 1.4891x over previous
#include <cuda_runtime.h>
#include <cstdint>
#include <cstddef>

#define BQ    2048
#define NTOK  98
#define DIMC  256
#define NHEAD 8
#define HD    32
#define NWIN  64
#define QK_SCALE 0.17677669529663687f   // 32^-0.5

#define NN2   (NTOK*NTOK)               // 9604
#define QKV_ELEMS ((size_t)BQ*NHEAD*NTOK*HD)   // 51,380,224

// ---------------- scratch (static device globals; no cudaMalloc allowed) ----
__device__ float g_q[QKV_ELEMS];
__device__ float g_k[QKV_ELEMS];
__device__ float g_v[QKV_ELEMS];
__device__ float g_o[(size_t)BQ*NTOK*DIMC];
__device__ float g_bias[NHEAD*NN2];
__device__ float g_wt_qkv[768*256];     // qkv_w transposed: [n][k]
__device__ float g_wt_proj[256*256];    // proj_w transposed: [n][k]

// ======================= helpers =============================================
__device__ __forceinline__ uint32_t smem_to_u32(const void* p) {
    uint32_t a;
    asm("{ .reg .u64 t; cvta.to.shared.u64 t, %1; cvt.u32.u64 %0, t; }"
        : "=r"(a) : "l"(p));
    return a;
}
__device__ __forceinline__ void cp_async16(uint32_t dst, const void* src) {
    asm volatile("cp.async.cg.shared.global [%0], [%1], 16;"
                 :: "r"(dst), "l"(src) : "memory");
}
#define CP_COMMIT() asm volatile("cp.async.commit_group;" ::: "memory")
#define CP_WAIT(n)  asm volatile("cp.async.wait_group %0;" :: "n"(n) : "memory")

// tf32 warp MMA: D(16x8) += A(16x8) * B(8x8)
__device__ __forceinline__ void mma_tf32(float* d, const uint32_t* a, const uint32_t* b) {
    asm volatile(
        "mma.sync.aligned.m16n8k8.row.col.f32.tf32.tf32.f32 "
        "{%0,%1,%2,%3}, {%4,%5,%6,%7}, {%8,%9}, {%0,%1,%2,%3};"
        : "+f"(d[0]), "+f"(d[1]), "+f"(d[2]), "+f"(d[3])
        : "r"(a[0]), "r"(a[1]), "r"(a[2]), "r"(a[3]), "r"(b[0]), "r"(b[1]));
}

// fp32 -> tf32 with round-to-nearest (unbiased; error ~2^-13 per element,
// accumulates as random walk over K instead of linearly like RZ truncation).
__device__ __forceinline__ uint32_t to_tf32(float f) {
    uint32_t h;
    asm("cvt.rna.tf32.f32 %0, %1;" : "=r"(h) : "f"(f));
    return h;
}

// ---------------- kernel: transpose weights (Wt[n][k] = W[k][n]) ------------
__global__ void transpose_w_kernel(const float* __restrict__ W, int N, int which)
{
    __shared__ float t[32][33];
    float* Wt = which ? g_wt_proj : g_wt_qkv;
    int n0 = blockIdx.x * 32, k0 = blockIdx.y * 32;
    int tx = threadIdx.x, ty = threadIdx.y;    // 32 x 8
    #pragma unroll
    for (int j = 0; j < 4; ++j)
        t[ty + j*8][tx] = W[(size_t)(k0 + ty + j*8) * N + n0 + tx];
    __syncthreads();
    #pragma unroll
    for (int j = 0; j < 4; ++j)
        Wt[(size_t)(n0 + ty + j*8) * 256 + k0 + tx] = t[tx][ty + j*8];
}

// ---------------- kernel: build per-head relative-position bias -------------
__global__ void bias_build_kernel(const float* __restrict__ table,
                                  const int*   __restrict__ rel)
{
    int t = blockIdx.x * blockDim.x + threadIdx.x;
    if (t < NHEAD * NN2) {
        int h  = t / NN2;
        int ij = t - h * NN2;
        g_bias[t] = table[rel[ij] * NHEAD + h];
    }
}

// ---------------- 1xTF32-RNA mma.sync GEMM: 128x128 tile, K=256 -------------
// smem per buffer: A[128][36] + B[128][36] floats = 36864 B; two buffers.
#define GPITCH 36
#define TILE_F (128 * GPITCH)                 // 4608 floats
#define BUF_F  (2 * TILE_F)                   // 9216 floats per buffer
#define GEMM_SMEM (2 * BUF_F * 4)             // 73728 bytes

template<bool IS_QKV>
__global__ void __launch_bounds__(256, 2)
gemm_mma_kernel(const float* __restrict__ Aq,   // QKV: x; proj: unused
                const float* __restrict__ bias,
                float* __restrict__ out)        // proj: d_out; QKV: unused
{
    extern __shared__ float smf[];
    uint32_t sb = smem_to_u32(smf);
    const int tid = threadIdx.x;
    const int wid = tid >> 5, lane = tid & 31;
    const int g = lane >> 2, tg = lane & 3;
    const int bm = blockIdx.x * 128;
    const int bn = blockIdx.y * 128;

    const float* A  = IS_QKV ? Aq : g_o;
    const float* Bt = IS_QKV ? g_wt_qkv : g_wt_proj;
    const int K = 256;

    const int r_  = tid >> 3;          // 0..31 base row
    const int c4_ = tid & 7;           // 0..7 16B segment within 32-f32 chunk

    float acc[4][4][4];
    #pragma unroll
    for (int am = 0; am < 4; ++am)
        #pragma unroll
        for (int an = 0; an < 4; ++an)
            #pragma unroll
            for (int j = 0; j < 4; ++j) acc[am][an][j] = 0.0f;

    auto issue = [&](int c, int buf) {
        int k0 = c * 32;
        uint32_t base = sb + (uint32_t)buf * (BUF_F * 4);
        #pragma unroll
        for (int i = 0; i < 4; ++i) {
            int r = r_ + i * 32;
            cp_async16(base + (uint32_t)(r * GPITCH * 4 + c4_ * 16),
                       A + (size_t)(bm + r) * K + k0 + c4_ * 4);
        }
        #pragma unroll
        for (int i = 0; i < 4; ++i) {
            int r = r_ + i * 32;
            cp_async16(base + (uint32_t)(TILE_F * 4 + r * GPITCH * 4 + c4_ * 16),
                       Bt + (size_t)(bn + r) * K + k0 + c4_ * 4);
        }
    };

    issue(0, 0);
    CP_COMMIT();

    const int mw = (wid >> 2) * 64;
    const int nw = (wid & 3) * 32;

    #pragma unroll 1
    for (int c = 0; c < 8; ++c) {
        if (c + 1 < 8) { issue(c + 1, (c + 1) & 1); CP_COMMIT(); CP_WAIT(1); }
        else           { CP_WAIT(0); }
        __syncthreads();

        const float* As = smf + (c & 1) * BUF_F;
        const float* Bs = As + TILE_F;

        #pragma unroll
        for (int s = 0; s < 4; ++s) {
            int k0 = s * 8 + tg;
            uint32_t b[4][2];
            #pragma unroll
            for (int an = 0; an < 4; ++an) {
                int base = (nw + 8 * an + g) * GPITCH + k0;
                b[an][0] = to_tf32(Bs[base]);
                b[an][1] = to_tf32(Bs[base + 4]);
            }
            #pragma unroll
            for (int am = 0; am < 4; ++am) {
                int base = (mw + 16 * am + g) * GPITCH + k0;
                uint32_t a[4];
                a[0] = to_tf32(As[base]);
                a[1] = to_tf32(As[base + 8 * GPITCH]);
                a[2] = to_tf32(As[base + 4]);
                a[3] = to_tf32(As[base + 8 * GPITCH + 4]);
                #pragma unroll
                for (int an = 0; an < 4; ++an)
                    mma_tf32(acc[am][an], a, b[an]);
            }
        }
        __syncthreads();
    }

    // -------- epilogue --------
    #pragma unroll
    for (int am = 0; am < 4; ++am) {
        #pragma unroll
        for (int half = 0; half < 2; ++half) {
            int m = bm + mw + 16 * am + g + 8 * half;
            if (IS_QKV) {
                int bwin = m / NTOK;
                int nn   = m - bwin * NTOK;
                #pragma unroll
                for (int an = 0; an < 4; ++an) {
                    int gcol = bn + nw + 8 * an + 2 * tg;
                    int sel  = gcol >> 8;
                    int h    = (gcol >> 5) & 7;
                    int d    = gcol & 31;
                    float* dst = (sel == 0 ? g_q : (sel == 1 ? g_k : g_v))
                               + (((size_t)bwin * NHEAD + h) * NTOK + nn) * HD + d;
                    float sc = (sel == 0) ? QK_SCALE : 1.0f;
                    float2 v;
                    v.x = (acc[am][an][2*half+0] + bias[gcol+0]) * sc;
                    v.y = (acc[am][an][2*half+1] + bias[gcol+1]) * sc;
                    *(float2*)dst = v;
                }
            } else {
                #pragma unroll
                for (int an = 0; an < 4; ++an) {
                    int gcol = bn + nw + 8 * an + 2 * tg;
                    float2 v;
                    v.x = acc[am][an][2*half+0] + bias[gcol+0];
                    v.y = acc[am][an][2*half+1] + bias[gcol+1];
                    *(float2*)(out + (size_t)m * DIMC + gcol) = v;
                }
            }
        }
    }
}

// ---------------- kernel: fused windowed attention --------------------------
#define SM_Q 0
#define SM_K 3234
#define SM_S 6468
#define ATTN_SMEM_BYTES (16072 * 4)

__global__ void __launch_bounds__(256) attn_kernel(const float* __restrict__ mask)
{
    extern __shared__ float sm[];
    float* Qs = sm + SM_Q;
    float* Ks = sm + SM_K;
    float* S  = sm + SM_S;

    int bid = blockIdx.x;
    int b = bid >> 3, h = bid & 7;
    int w = b & (NWIN - 1);
    int tid = threadIdx.x;
    int tx = tid & 15, ty = tid >> 4;

    const float* qp = g_q + (size_t)bid * (NTOK * HD);
    const float* kp = g_k + (size_t)bid * (NTOK * HD);
    const float* vp = g_v + (size_t)bid * (NTOK * HD);

    for (int t = tid; t < (NTOK * HD) / 4; t += 256) {
        float4 q4 = ((const float4*)qp)[t];
        float4 k4 = ((const float4*)kp)[t];
        int i = t >> 3, seg = (t & 7) * 4;
        float* qd = Qs + i*33 + seg;
        float* kd = Ks + i*33 + seg;
        qd[0]=q4.x; qd[1]=q4.y; qd[2]=q4.z; qd[3]=q4.w;
        kd[0]=k4.x; kd[1]=k4.y; kd[2]=k4.z; kd[3]=k4.w;
    }
    __syncthreads();

    float acc[7][7];
    #pragma unroll
    for (int r = 0; r < 7; ++r)
        #pragma unroll
        for (int s2 = 0; s2 < 7; ++s2) acc[r][s2] = 0.0f;

    for (int kk = 0; kk < HD; ++kk) {
        float qv[7], kv[7];
        #pragma unroll
        for (int r = 0; r < 7; ++r) {
            int i = ty + 16*r; i = (i < NTOK) ? i : (NTOK - 1);
            qv[r] = Qs[i*33 + kk];
        }
        #pragma unroll
        for (int s2 = 0; s2 < 7; ++s2) {
            int j = tx + 16*s2; j = (j < NTOK) ? j : (NTOK - 1);
            kv[s2] = Ks[j*33 + kk];
        }
        #pragma unroll
        for (int r = 0; r < 7; ++r)
            #pragma unroll
            for (int s2 = 0; s2 < 7; ++s2)
                acc[r][s2] = fmaf(qv[r], kv[s2], acc[r][s2]);
    }

    const float* bptr = g_bias + h * NN2;
    const float* mptr = mask + w * NN2;
    #pragma unroll
    for (int r = 0; r < 7; ++r) {
        int i = ty + 16*r;
        if (i < NTOK) {
            #pragma unroll
            for (int s2 = 0; s2 < 7; ++s2) {
                int j = tx + 16*s2;
                if (j < NTOK)
                    S[i*NTOK + j] = acc[r][s2] + bptr[i*NTOK + j] + mptr[i*NTOK + j];
            }
        }
    }
    __syncthreads();

    for (int t = tid; t < (NTOK * HD) / 4; t += 256) {
        float4 v4 = ((const float4*)vp)[t];
        int i = t >> 3, seg = (t & 7) * 4;
        float* vd = Qs + i*33 + seg;
        vd[0]=v4.x; vd[1]=v4.y; vd[2]=v4.z; vd[3]=v4.w;
    }

    int warp = tid >> 5, lane = tid & 31;
    for (int r = warp; r < NTOK; r += 8) {
        float* row = S + r * NTOK;
        float v0 = row[lane];
        float v1 = row[32 + lane];
        float v2 = row[64 + lane];
        float v3 = (lane < 2) ? row[96 + lane] : -1e30f;
        float mx = fmaxf(fmaxf(v0, v1), fmaxf(v2, v3));
        #pragma unroll
        for (int o = 16; o > 0; o >>= 1) mx = fmaxf(mx, __shfl_xor_sync(0xffffffffu, mx, o));
        float e0 = __expf(v0 - mx), e1 = __expf(v1 - mx), e2 = __expf(v2 - mx);
        float e3 = (lane < 2) ? __expf(v3 - mx) : 0.0f;
        float sum = e0 + e1 + e2 + e3;
        #pragma unroll
        for (int o = 16; o > 0; o >>= 1) sum += __shfl_xor_sync(0xffffffffu, sum, o);
        float inv = 1.0f / sum;
        row[lane]      = e0 * inv;
        row[32 + lane] = e1 * inv;
        row[64 + lane] = e2 * inv;
        if (lane < 2) row[96 + lane] = e3 * inv;
    }
    __syncthreads();

    float o0[7], o1[7];
    #pragma unroll
    for (int r = 0; r < 7; ++r) { o0[r] = 0.0f; o1[r] = 0.0f; }

    for (int j = 0; j < NTOK; ++j) {
        float v0 = Qs[j*33 + tx];
        float v1 = Qs[j*33 + 16 + tx];
        #pragma unroll
        for (int r = 0; r < 7; ++r) {
            int i = ty + 16*r;
            if (i < NTOK) {
                float p = S[i*NTOK + j];
                o0[r] = fmaf(p, v0, o0[r]);
                o1[r] = fmaf(p, v1, o1[r]);
            }
        }
    }

    float* op = g_o + (size_t)b * NTOK * DIMC + h * HD;
    #pragma unroll
    for (int r = 0; r < 7; ++r) {
        int i = ty + 16*r;
        if (i < NTOK) {
            op[(size_t)i * DIMC + tx]      = o0[r];
            op[(size_t)i * DIMC + 16 + tx] = o1[r];
        }
    }
}

// ---------------- launch -----------------------------------------------------
extern "C" void kernel_launch(void* const* d_in, const int* in_sizes, int n_in,
                              void* d_out, int out_size)
{
    const float* x          = (const float*)d_in[0];
    const float* mask       = (const float*)d_in[1];
    const float* qkv_w      = (const float*)d_in[2];
    const float* qkv_b      = (const float*)d_in[3];
    const float* proj_w     = (const float*)d_in[4];
    const float* proj_b     = (const float*)d_in[5];
    const float* bias_table = (const float*)d_in[6];
    const int*   rel_index  = (const int*)d_in[7];
    float* out = (float*)d_out;

    cudaFuncSetAttribute(gemm_mma_kernel<true>,
                         cudaFuncAttributeMaxDynamicSharedMemorySize, GEMM_SMEM);
    cudaFuncSetAttribute(gemm_mma_kernel<false>,
                         cudaFuncAttributeMaxDynamicSharedMemorySize, GEMM_SMEM);
    cudaFuncSetAttribute(attn_kernel,
                         cudaFuncAttributeMaxDynamicSharedMemorySize, ATTN_SMEM_BYTES);

    transpose_w_kernel<<<dim3(24, 8), dim3(32, 8)>>>(qkv_w, 768, 0);
    transpose_w_kernel<<<dim3(8, 8),  dim3(32, 8)>>>(proj_w, 256, 1);
    bias_build_kernel<<<(NHEAD * NN2 + 255) / 256, 256>>>(bias_table, rel_index);

    gemm_mma_kernel<true><<<dim3(1568, 6), 256, GEMM_SMEM>>>(x, qkv_b, nullptr);

    attn_kernel<<<BQ * NHEAD, 256, ATTN_SMEM_BYTES>>>(mask);

    gemm_mma_kernel<false><<<dim3(1568, 2), 256, GEMM_SMEM>>>(nullptr, proj_b, out);
}